// round 4
// baseline (speedup 1.0000x reference)
#include <cuda_runtime.h>

#define T_LEN 2048
#define C_ 8
#define M_ 100
#define MPAD 128
#define N_ 16
#define NTHREADS 512
#define L2E 1.4426950408889634f

// smem layout (bytes)
#define PHI_OFF   0           // u64 [8][4][128] = 32768 B
#define PART_OFF  32768       // float [4*8][134] = 17152 B
#define STATE_OFF 49920       // float [4][16] = 256 B
#define SQ_OFF    50176       // float [4][4] = 64 B
#define SMEM_BYTES 50304
#define PART_STRIDE 134

__device__ float g_gate[(size_t)T_LEN * 512 * C_];   // [t][b][c]

typedef unsigned long long u64;

__device__ __forceinline__ u64 ffma2(u64 a, u64 b, u64 c) {
    u64 d; asm("fma.rn.f32x2 %0, %1, %2, %3;" : "=l"(d) : "l"(a), "l"(b), "l"(c)); return d;
}
__device__ __forceinline__ u64 pack2(float lo, float hi) {
    u64 d; asm("mov.b64 %0, {%1, %2};" : "=l"(d) : "f"(lo), "f"(hi)); return d;
}
__device__ __forceinline__ void unpack2(u64 v, float& lo, float& hi) {
    asm("mov.b64 {%0, %1}, %2;" : "=f"(lo), "=f"(hi) : "l"(v));
}
__device__ __forceinline__ float ex2f(float a) {
    float r; asm("ex2.approx.f32 %0, %1;" : "=f"(r) : "f"(a)); return r;
}

// ---------- gate pre-pass ----------
__global__ void gate_kernel(const float* __restrict__ x,
                            const float* __restrict__ W1, const float* __restrict__ b1,
                            const float* __restrict__ W2, const float* __restrict__ b2,
                            int B) {
    int idx = blockIdx.x * blockDim.x + threadIdx.x;   // t*B + b
    if (idx >= B * T_LEN) return;
    int t = idx / B, b = idx - t * B;
    float xv = __ldg(&x[(size_t)b * T_LEN + t]);
    float lg[C_];
    #pragma unroll
    for (int c = 0; c < C_; c++) lg[c] = __ldg(&b2[c]);
    #pragma unroll
    for (int j = 0; j < 16; j++) {
        float h = fmaxf(0.f, fmaf(xv, __ldg(&W1[j]), __ldg(&b1[j])));
        #pragma unroll
        for (int c = 0; c < C_; c++) lg[c] = fmaf(h, __ldg(&W2[j * C_ + c]), lg[c]);
    }
    float mx = lg[0];
    #pragma unroll
    for (int c = 1; c < C_; c++) mx = fmaxf(mx, lg[c]);
    float e[C_], se = 0.f;
    #pragma unroll
    for (int c = 0; c < C_; c++) { e[c] = __expf(lg[c] - mx); se += e[c]; }
    float inv = 1.f / se;
    float* dst = &g_gate[(size_t)idx * C_];
    #pragma unroll
    for (int c = 0; c < C_; c++) dst[c] = e[c] * inv;
}

// ---------- main recurrence: 512 threads, 4 batches, 3 balanced phases ----------
__global__ __launch_bounds__(NTHREADS, 1)
void kaarma_kernel(const float* __restrict__ x, const float* __restrict__ S,
                   const float* __restrict__ U, const float* __restrict__ A,
                   float* __restrict__ out, int B) {
    extern __shared__ __align__(16) char smraw[];
    u64*   phi      = (u64*)(smraw + PHI_OFF);       // [c][b][m] duplicated (phi,phi)
    float* partial  = (float*)(smraw + PART_OFF);    // [(b*8+c)][134]
    float* state_sh = (float*)(smraw + STATE_OFF);   // [4][16]
    float* sq_sh    = (float*)(smraw + SQ_OFF);      // [4][4]

    const int tid = threadIdx.x;
    const int b0  = blockIdx.x * 4;

    // phase-1 ids: 2 adjacent m-rows per thread
    const int c1 = tid >> 6, mp = tid & 63;          // rows m = 2mp, 2mp+1 (padded to 128)
    // phase-2 ids
    const int c2 = tid >> 6, np = (tid >> 3) & 7, mo = tid & 7;   // 16 m's, n-pair
    // phase-3 ids
    const int rb = tid >> 7, rn = (tid >> 3) & 15, rc = tid & 7;

    // ---- init dictionaries (log2-domain prescale) ----
    u64 S2[2][8]; float U2l[2], Rn[2];
    #pragma unroll
    for (int r = 0; r < 2; r++) {
        int m = 2 * mp + r;
        if (m < M_) {
            const int base = (c1 * M_ + m) * N_;
            float sv[N_], rr = 0.f;
            #pragma unroll
            for (int n = 0; n < N_; n++) { sv[n] = S[base + n]; rr = fmaf(sv[n], sv[n], rr); }
            float uv = U[c1 * M_ + m];
            Rn[r]  = -L2E * fmaf(uv, uv, rr);
            U2l[r] = 2.f * L2E * uv;
            #pragma unroll
            for (int j = 0; j < 8; j++)
                S2[r][j] = pack2(2.f * L2E * sv[2 * j], 2.f * L2E * sv[2 * j + 1]);
        } else {
            Rn[r] = 0.f; U2l[r] = 0.f;
            #pragma unroll
            for (int j = 0; j < 8; j++) S2[r][j] = 0ull;
        }
    }
    u64 A2[16];
    #pragma unroll
    for (int k = 0; k < 16; k++) {
        int m = 16 * mo + k;
        A2[k] = (m < M_) ? pack2(A[(c2 * M_ + m) * N_ + 2 * np],
                                 A[(c2 * M_ + m) * N_ + 2 * np + 1])
                         : 0ull;
    }
    if (tid < 64) state_sh[tid] = 0.f;
    if (tid < 16) sq_sh[tid] = 0.f;
    __syncthreads();

    const float* xrow = x + (size_t)b0 * T_LEN;
    float f_reg = 0.f;   // unused at t=0 beyond formula (ssq=0)

    for (int t = 0; t < T_LEN; t++) {
        // ---- top: x loads, gate prefetch, per-batch factor f ----
        float xb[4];
        #pragma unroll
        for (int b = 0; b < 4; b++) xb[b] = __ldg(xrow + (size_t)b * T_LEN + t);
        float gate_r = __ldg(&g_gate[((size_t)t * B + b0 + rb) * C_ + rc]);
        {
            const float4 s4 = *(const float4*)&sq_sh[rb * 4];   // sum of nv^2 from prev step
            float ssq = (s4.x + s4.y) + (s4.z + s4.w);
            float xB = xb[rb];
            f_reg = ex2f(-L2E * fmaf(xB, xB, ssq));   // exp(-(||s||^2 + x^2))
        }

        // ---- phase 1: phi~ = exp2(2L2E*s.S + 2L2E*x*U - L2E*(||S||^2+U^2)) ----
        {
            u64* phiw = &phi[(size_t)(c1 * 4) * MPAD + 2 * mp];
            #pragma unroll
            for (int b = 0; b < 4; b++) {
                const ulonglong2* sp = (const ulonglong2*)(state_sh + b * 16);
                u64 st[8];
                #pragma unroll
                for (int j = 0; j < 4; j++) {
                    ulonglong2 v = sp[j];
                    st[2 * j] = v.x; st[2 * j + 1] = v.y;
                }
                u64 d0 = 0ull, d1 = 0ull;
                #pragma unroll
                for (int j = 0; j < 8; j++) {
                    d0 = ffma2(st[j], S2[0][j], d0);
                    d1 = ffma2(st[j], S2[1][j], d1);
                }
                float l0, h0, l1, h1;
                unpack2(d0, l0, h0); unpack2(d1, l1, h1);
                float p0 = ex2f((l0 + h0) + fmaf(xb[b], U2l[0], Rn[0]));
                float p1 = ex2f((l1 + h1) + fmaf(xb[b], U2l[1], Rn[1]));
                *(ulonglong2*)(phiw + (size_t)b * MPAD) =
                    make_ulonglong2(pack2(p0, p0), pack2(p1, p1));
            }
        }
        __syncthreads();

        // ---- phase 2: partial[b][c][npair] += phi~ @ A over 16 m's ----
        {
            #pragma unroll
            for (int b = 0; b < 4; b++) {
                const ulonglong2* pb =
                    (const ulonglong2*)&phi[((size_t)(c2 * 4 + b)) * MPAD + 16 * mo];
                u64 acc = 0ull;
                #pragma unroll
                for (int j = 0; j < 8; j++) {
                    ulonglong2 q = pb[j];
                    acc = ffma2(q.x, A2[2 * j], acc);
                    acc = ffma2(q.y, A2[2 * j + 1], acc);
                }
                *(u64*)&partial[(b * 8 + c2) * PART_STRIDE + np * 16 + 2 * mo] = acc;
            }
        }
        __syncthreads();

        // ---- phase 3: reduce over m-octiles, gate, reduce over c, update state ----
        {
            const float* pbase =
                &partial[(rb * 8 + rc) * PART_STRIDE + (rn >> 1) * 16 + (rn & 1)];
            float v = 0.f;
            #pragma unroll
            for (int m8 = 0; m8 < 8; m8++) v += pbase[2 * m8];
            v *= gate_r;
            #pragma unroll
            for (int o = 1; o < 8; o <<= 1) v += __shfl_xor_sync(0xffffffffu, v, o);
            float nv = v * f_reg;                    // final state component (rb, rn)
            // ||s_new||^2 partial: butterfly nv^2 over the 4 n's in this warp
            float w = nv * nv;
            w += __shfl_xor_sync(0xffffffffu, w, 8);
            w += __shfl_xor_sync(0xffffffffu, w, 16);
            if ((tid & 31) == 0) sq_sh[((tid >> 7) << 2) | ((tid >> 5) & 3)] = w;
            if (rc == 0) {
                state_sh[rb * 16 + rn] = nv;
                if (rn == N_ - 1) out[(size_t)(b0 + rb) * T_LEN + t] = nv;
            }
        }
        __syncthreads();
    }
}

extern "C" void kernel_launch(void* const* d_in, const int* in_sizes, int n_in,
                              void* d_out, int out_size) {
    const float* x  = (const float*)d_in[0];
    const float* S  = (const float*)d_in[1];
    const float* U  = (const float*)d_in[2];
    const float* A  = (const float*)d_in[3];
    const float* W1 = (const float*)d_in[4];
    const float* b1 = (const float*)d_in[5];
    const float* W2 = (const float*)d_in[6];
    const float* b2 = (const float*)d_in[7];
    const int B = in_sizes[0] / T_LEN;   // 512

    static int smem_set = 0;
    if (!smem_set) {
        cudaFuncSetAttribute(kaarma_kernel,
                             cudaFuncAttributeMaxDynamicSharedMemorySize, SMEM_BYTES);
        smem_set = 1;
    }
    gate_kernel<<<(B * T_LEN + 255) / 256, 256>>>(x, W1, b1, W2, b2, B);
    kaarma_kernel<<<B / 4, NTHREADS, SMEM_BYTES>>>(x, S, U, A, (float*)d_out, B);
}

// round 7
// speedup vs baseline: 3.1492x; 3.1492x over previous
#include <cuda_runtime.h>

#define T_LEN 2048
#define C_ 8
#define N_ 16
#define NTHREADS 384
#define NSLOTS 192                 // 8 cells * 24 slots
#define SLOT_STRIDE 10             // u64 per slot row (8 used + 2 pad)
#define L2E 1.4426950408889634f

// smem: partial u64[4][192][10] = 61440 B, state 256 B, gate 256 B, f 16 B
#define PART_U64   (4 * NSLOTS * SLOT_STRIDE)
#define SMEM_BYTES (PART_U64 * 8 + 256 + 256 + 16)

__device__ float g_lgate[(size_t)T_LEN * 512 * C_];   // log2(gate) [t][b][c]

typedef unsigned long long u64;

__device__ __forceinline__ u64 ffma2(u64 a, u64 b, u64 c) {
    u64 d; asm("fma.rn.f32x2 %0, %1, %2, %3;" : "=l"(d) : "l"(a), "l"(b), "l"(c)); return d;
}
__device__ __forceinline__ u64 pack2(float lo, float hi) {
    u64 d; asm("mov.b64 %0, {%1, %2};" : "=l"(d) : "f"(lo), "f"(hi)); return d;
}
__device__ __forceinline__ void unpack2(u64 v, float& lo, float& hi) {
    asm("mov.b64 {%0, %1}, %2;" : "=f"(lo), "=f"(hi) : "l"(v));
}
__device__ __forceinline__ float ex2f(float a) {
    float r; asm("ex2.approx.f32 %0, %1;" : "=f"(r) : "f"(a)); return r;
}
// packed (1.0,1.0) for add-via-fma: a*1 + b is exact
#define ONE2 0x3f8000003f800000ull
__device__ __forceinline__ u64 fadd2(u64 a, u64 b) { return ffma2(a, ONE2, b); }

// ---------- gate pre-pass: log2(softmax) ----------
__global__ void gate_kernel(const float* __restrict__ x,
                            const float* __restrict__ W1, const float* __restrict__ b1,
                            const float* __restrict__ W2, const float* __restrict__ b2,
                            int B) {
    int idx = blockIdx.x * blockDim.x + threadIdx.x;   // t*B + b
    if (idx >= B * T_LEN) return;
    int t = idx / B, b = idx - t * B;
    float xv = __ldg(&x[(size_t)b * T_LEN + t]);
    float lg[C_];
    #pragma unroll
    for (int c = 0; c < C_; c++) lg[c] = __ldg(&b2[c]);
    #pragma unroll
    for (int j = 0; j < 16; j++) {
        float h = fmaxf(0.f, fmaf(xv, __ldg(&W1[j]), __ldg(&b1[j])));
        #pragma unroll
        for (int c = 0; c < C_; c++) lg[c] = fmaf(h, __ldg(&W2[j * C_ + c]), lg[c]);
    }
    float mx = lg[0];
    #pragma unroll
    for (int c = 1; c < C_; c++) mx = fmaxf(mx, lg[c]);
    float se = 0.f;
    #pragma unroll
    for (int c = 0; c < C_; c++) se += __expf(lg[c] - mx);
    float lse = __log2f(se);
    float* dst = &g_lgate[(size_t)idx * C_];
    #pragma unroll
    for (int c = 0; c < C_; c++) dst[c] = (lg[c] - mx) * L2E - lse;   // log2(gate_c)
}

// ---------- main recurrence: 384 threads, n-half split, 4 batches ----------
__global__ __launch_bounds__(NTHREADS, 1)
void kaarma_kernel(const float* __restrict__ x, const float* __restrict__ S,
                   const float* __restrict__ U, const float* __restrict__ A,
                   float* __restrict__ out, int B) {
    extern __shared__ __align__(16) char smraw[];
    u64*   part     = (u64*)smraw;                          // [4][192][10]
    float* state_sh = (float*)(smraw + PART_U64 * 8);       // [4][16]
    float* gate_sh  = state_sh + 64;                        // [2][32]
    float* f_sh     = gate_sh + 64;                         // [4]

    const int tid = threadIdx.x;
    const int b0  = blockIdx.x * 4;

    const int nh = tid & 1;          // n-half: 0 -> n[0..7], 1 -> n[8..15]
    const int s  = tid >> 1;         // slot 0..191
    const int c  = s / 24;
    const int j  = s - c * 24;       // 0..23:  j<20 -> 4 rows,  j>=20 -> 5 rows
    const int nr = (j < 20) ? 4 : 5;
    const int r0 = (j < 20) ? j * 4 : 80 + (j - 20) * 5;   // local row base within cell

    // dictionary halves (log2-domain prescale); rows >= nr zero-filled (contribute 0)
    u64 S2h[5][4], A2h[5][4];
    float U2l[5], Rn[5];
    #pragma unroll
    for (int i = 0; i < 5; i++) {
        if (i < nr) {
            const int g    = c * 100 + r0 + i;               // global row
            const int base = g * N_;
            float sv[N_], rr = 0.f;
            #pragma unroll
            for (int n = 0; n < N_; n++) { sv[n] = S[base + n]; rr = fmaf(sv[n], sv[n], rr); }
            float uv = U[g];
            Rn[i]  = -L2E * fmaf(uv, uv, rr);
            U2l[i] = 2.f * L2E * uv;
            #pragma unroll
            for (int q = 0; q < 4; q++) {
                int n0 = nh * 8 + 2 * q;
                S2h[i][q] = pack2(2.f * L2E * sv[n0], 2.f * L2E * sv[n0 + 1]);
                A2h[i][q] = pack2(A[base + n0], A[base + n0 + 1]);
            }
        } else {
            Rn[i] = 0.f; U2l[i] = 0.f;
            #pragma unroll
            for (int q = 0; q < 4; q++) { S2h[i][q] = 0ull; A2h[i][q] = 0ull; }
        }
    }
    if (tid < 64) state_sh[tid] = 0.f;
    if (tid < 32) gate_sh[tid] = __ldg(&g_lgate[(size_t)b0 * C_ + tid]);   // t=0 buffer
    __syncthreads();

    const float* xrow = x + (size_t)b0 * T_LEN;

    for (int t = 0; t < T_LEN; t++) {
        const int cur = t & 1;
        float xv[4];
        #pragma unroll
        for (int b = 0; b < 4; b++) xv[b] = __ldg(xrow + (size_t)b * T_LEN + t);

        // side duties (predicated into warps 8/9, overlapped with main FMA)
        if (tid >= 256 && tid < 260) {
            const int b = tid - 256;                          // f_b = exp(-(||s||^2+x^2))
            float q = xv[b] * xv[b];
            #pragma unroll
            for (int n = 0; n < N_; n++) {
                float sv = state_sh[b * 16 + n];
                q = fmaf(sv, sv, q);
            }
            f_sh[b] = ex2f(-L2E * q);
        }
        if (tid >= 288 && tid < 320) {                        // prefetch next lgate
            const int lane = tid - 288;
            int tn = (t + 1 < T_LEN) ? t + 1 : t;
            gate_sh[(cur ^ 1) * 32 + lane] =
                __ldg(&g_lgate[((size_t)tn * B + b0) * C_ + lane]);
        }

        // main: two passes over batch pairs
        #pragma unroll
        for (int p = 0; p < 2; p++) {
            const int ba = 2 * p, bb = 2 * p + 1;
            const float xa = xv[ba], xb = xv[bb];
            const float lga = gate_sh[cur * 32 + ba * C_ + c];
            const float lgb = gate_sh[cur * 32 + bb * C_ + c];
            const u64* sta = (const u64*)(state_sh + ba * 16 + nh * 8);
            const u64* stb = (const u64*)(state_sh + bb * 16 + nh * 8);
            u64 sa[4], sb[4], acca[4], accb[4];
            #pragma unroll
            for (int q = 0; q < 4; q++) {
                sa[q] = sta[q]; sb[q] = stb[q];
                acca[q] = 0ull; accb[q] = 0ull;
            }
            #pragma unroll
            for (int i = 0; i < 5; i++) {
                u64 da = 0ull, db = 0ull;
                #pragma unroll
                for (int q = 0; q < 4; q++) {
                    da = ffma2(sa[q], S2h[i][q], da);
                    db = ffma2(sb[q], S2h[i][q], db);
                }
                float la, ha, lb, hb;
                unpack2(da, la, ha); unpack2(db, lb, hb);
                float dsa = la + ha, dsb = lb + hb;
                dsa += __shfl_xor_sync(0xffffffffu, dsa, 1);   // other n-half
                dsb += __shfl_xor_sync(0xffffffffu, dsb, 1);
                float pa = ex2f(dsa + fmaf(xa, U2l[i], Rn[i] + lga));
                float pb = ex2f(dsb + fmaf(xb, U2l[i], Rn[i] + lgb));
                u64 pap = pack2(pa, pa), pbp = pack2(pb, pb);
                #pragma unroll
                for (int q = 0; q < 4; q++) {
                    acca[q] = ffma2(pap, A2h[i][q], acca[q]);
                    accb[q] = ffma2(pbp, A2h[i][q], accb[q]);
                }
            }
            u64* da_ = part + ((size_t)(ba * NSLOTS + s)) * SLOT_STRIDE + nh * 4;
            u64* db_ = part + ((size_t)(bb * NSLOTS + s)) * SLOT_STRIDE + nh * 4;
            *(ulonglong2*)(da_)     = make_ulonglong2(acca[0], acca[1]);
            *(ulonglong2*)(da_ + 2) = make_ulonglong2(acca[2], acca[3]);
            *(ulonglong2*)(db_)     = make_ulonglong2(accb[0], accb[1]);
            *(ulonglong2*)(db_ + 2) = make_ulonglong2(accb[2], accb[3]);
        }
        __syncthreads();

        // reduction: 256 threads = (b, npair, q); sum 24 slots each, then shfl over q
        if (tid < 256) {
            const int rb = tid >> 6, np = (tid >> 3) & 7, q = tid & 7;
            const u64* pr = part + ((size_t)(rb * NSLOTS + q * 24)) * SLOT_STRIDE + np;
            u64 v = pr[0];
            #pragma unroll
            for (int i = 1; i < 24; i++) v = fadd2(v, pr[(size_t)i * SLOT_STRIDE]);
            #pragma unroll
            for (int o = 1; o < 8; o <<= 1)
                v = fadd2(v, __shfl_xor_sync(0xffffffffu, v, o));
            if (q == 0) {
                float v0, v1;
                unpack2(v, v0, v1);
                const float f = f_sh[rb];
                float nv0 = v0 * f, nv1 = v1 * f;
                state_sh[rb * 16 + 2 * np]     = nv0;
                state_sh[rb * 16 + 2 * np + 1] = nv1;
                if (np == 7) out[(size_t)(b0 + rb) * T_LEN + t] = nv1;   // n = 15
            }
        }
        __syncthreads();
    }
}

extern "C" void kernel_launch(void* const* d_in, const int* in_sizes, int n_in,
                              void* d_out, int out_size) {
    const float* x  = (const float*)d_in[0];
    const float* S  = (const float*)d_in[1];
    const float* U  = (const float*)d_in[2];
    const float* A  = (const float*)d_in[3];
    const float* W1 = (const float*)d_in[4];
    const float* b1 = (const float*)d_in[5];
    const float* W2 = (const float*)d_in[6];
    const float* b2 = (const float*)d_in[7];
    const int B = in_sizes[0] / T_LEN;   // 512

    static int smem_set = 0;
    if (!smem_set) {
        cudaFuncSetAttribute(kaarma_kernel,
                             cudaFuncAttributeMaxDynamicSharedMemorySize, SMEM_BYTES);
        smem_set = 1;
    }
    gate_kernel<<<(B * T_LEN + 255) / 256, 256>>>(x, W1, b1, W2, b2, B);
    kaarma_kernel<<<B / 4, NTHREADS, SMEM_BYTES>>>(x, S, U, A, (float*)d_out, B);
}

// round 9
// speedup vs baseline: 5.9500x; 1.8894x over previous
#include <cuda_runtime.h>

#define T_LEN 2048
#define C_ 8
#define N_ 16
#define NTHREADS 384
#define NSLOTS 192                 // 8 cells * 24 slots (flat, gate folded into phi)
#define STR 6                      // u64 per half-slot (4 used + 2 pad)
#define HALF_U64 (4 * NSLOTS * STR)        // 4608
#define NHOFF (HALF_U64 + 8)               // 4616: half-1 base; 4616 mod 16 = 8
#define PART_TOTAL (NHOFF + HALF_U64)      // 9224 u64
#define SMEM_BYTES (PART_TOTAL * 8 + 256 + 256 + 16)
#define L2E 1.4426950408889634f

__device__ float g_lgate[(size_t)T_LEN * 512 * C_];   // log2(gate) [t][b][c]

typedef unsigned long long u64;

__device__ __forceinline__ u64 ffma2(u64 a, u64 b, u64 c) {
    u64 d; asm("fma.rn.f32x2 %0, %1, %2, %3;" : "=l"(d) : "l"(a), "l"(b), "l"(c)); return d;
}
__device__ __forceinline__ u64 pack2(float lo, float hi) {
    u64 d; asm("mov.b64 %0, {%1, %2};" : "=l"(d) : "f"(lo), "f"(hi)); return d;
}
__device__ __forceinline__ void unpack2(u64 v, float& lo, float& hi) {
    asm("mov.b64 {%0, %1}, %2;" : "=f"(lo), "=f"(hi) : "l"(v));
}
__device__ __forceinline__ float ex2f(float a) {
    float r; asm("ex2.approx.f32 %0, %1;" : "=f"(r) : "f"(a)); return r;
}
#define ONE2 0x3f8000003f800000ull
__device__ __forceinline__ u64 fadd2(u64 a, u64 b) { return ffma2(a, ONE2, b); }

// ---------- gate pre-pass: log2(softmax) ----------
__global__ void gate_kernel(const float* __restrict__ x,
                            const float* __restrict__ W1, const float* __restrict__ b1,
                            const float* __restrict__ W2, const float* __restrict__ b2,
                            int B) {
    int idx = blockIdx.x * blockDim.x + threadIdx.x;   // t*B + b
    if (idx >= B * T_LEN) return;
    int t = idx / B, b = idx - t * B;
    float xv = __ldg(&x[(size_t)b * T_LEN + t]);
    float lg[C_];
    #pragma unroll
    for (int c = 0; c < C_; c++) lg[c] = __ldg(&b2[c]);
    #pragma unroll
    for (int j = 0; j < 16; j++) {
        float h = fmaxf(0.f, fmaf(xv, __ldg(&W1[j]), __ldg(&b1[j])));
        #pragma unroll
        for (int c = 0; c < C_; c++) lg[c] = fmaf(h, __ldg(&W2[j * C_ + c]), lg[c]);
    }
    float mx = lg[0];
    #pragma unroll
    for (int c = 1; c < C_; c++) mx = fmaxf(mx, lg[c]);
    float se = 0.f;
    #pragma unroll
    for (int c = 0; c < C_; c++) se += __expf(lg[c] - mx);
    float lse = __log2f(se);
    float* dst = &g_lgate[(size_t)idx * C_];
    #pragma unroll
    for (int c = 0; c < C_; c++) dst[c] = (lg[c] - mx) * L2E - lse;   // log2(gate_c)
}

// ---------- main recurrence: 384 threads, n-half split, 4 batches ----------
__global__ __launch_bounds__(NTHREADS, 1)
void kaarma_kernel(const float* __restrict__ x, const float* __restrict__ S,
                   const float* __restrict__ U, const float* __restrict__ A,
                   float* __restrict__ out, int B) {
    extern __shared__ __align__(16) char smraw[];
    u64*   part     = (u64*)smraw;                          // two half-buffers
    float* state_sh = (float*)(smraw + PART_TOTAL * 8);     // [4][16]
    float* gate_sh  = state_sh + 64;                        // [2][32]
    float* f_sh     = gate_sh + 64;                         // [4]

    const int tid = threadIdx.x;
    const int b0  = blockIdx.x * 4;

    const int nh = tid & 1;          // n-half: 0 -> n[0..7], 1 -> n[8..15]
    const int s  = tid >> 1;         // slot 0..191
    const int c  = s / 24;
    const int j  = s - c * 24;       // j<20 -> 4 rows, j>=20 -> 5 rows
    const int nr = (j < 20) ? 4 : 5;
    const int r0 = (j < 20) ? j * 4 : 80 + (j - 20) * 5;

    // dictionary halves (log2-domain prescale); padded rows zero -> contribute 0
    u64 S2h[5][4], A2h[5][4];
    float U2l[5], Rn[5];
    #pragma unroll
    for (int i = 0; i < 5; i++) {
        if (i < nr) {
            const int g    = c * 100 + r0 + i;
            const int base = g * N_;
            float sv[N_], rr = 0.f;
            #pragma unroll
            for (int n = 0; n < N_; n++) { sv[n] = S[base + n]; rr = fmaf(sv[n], sv[n], rr); }
            float uv = U[g];
            Rn[i]  = -L2E * fmaf(uv, uv, rr);
            U2l[i] = 2.f * L2E * uv;
            #pragma unroll
            for (int q = 0; q < 4; q++) {
                int n0 = nh * 8 + 2 * q;
                S2h[i][q] = pack2(2.f * L2E * sv[n0], 2.f * L2E * sv[n0 + 1]);
                A2h[i][q] = pack2(A[base + n0], A[base + n0 + 1]);
            }
        } else {
            Rn[i] = 0.f; U2l[i] = 0.f;
            #pragma unroll
            for (int q = 0; q < 4; q++) { S2h[i][q] = 0ull; A2h[i][q] = 0ull; }
        }
    }
    if (tid < 64) state_sh[tid] = 0.f;
    if (tid < 32) gate_sh[tid] = __ldg(&g_lgate[(size_t)b0 * C_ + tid]);   // t=0 buffer
    __syncthreads();

    const float* xrow = x + (size_t)b0 * T_LEN;
    const size_t nhbase = (size_t)nh * NHOFF;

    for (int t = 0; t < T_LEN; t++) {
        const int cur = t & 1;
        float xv[4];
        #pragma unroll
        for (int b = 0; b < 4; b++) xv[b] = __ldg(xrow + (size_t)b * T_LEN + t);

        // side duties (overlapped with main FMA)
        if (tid >= 256 && tid < 260) {
            const int b = tid - 256;                   // f_b = exp(-(||s||^2+x^2))
            float q = xv[b] * xv[b];
            #pragma unroll
            for (int n = 0; n < N_; n++) {
                float sv = state_sh[b * 16 + n];
                q = fmaf(sv, sv, q);
            }
            f_sh[b] = ex2f(-L2E * q);
        }
        if (tid >= 288 && tid < 320) {                 // prefetch next lgate
            const int lane = tid - 288;
            int tn = (t + 1 < T_LEN) ? t + 1 : t;
            gate_sh[(cur ^ 1) * 32 + lane] =
                __ldg(&g_lgate[((size_t)tn * B + b0) * C_ + lane]);
        }

        // main: two passes over batch pairs
        #pragma unroll
        for (int p = 0; p < 2; p++) {
            const int ba = 2 * p, bb = 2 * p + 1;
            const float xa = xv[ba], xb = xv[bb];
            const float lga = gate_sh[cur * 32 + ba * C_ + c];
            const float lgb = gate_sh[cur * 32 + bb * C_ + c];
            const u64* sta = (const u64*)(state_sh + ba * 16 + nh * 8);
            const u64* stb = (const u64*)(state_sh + bb * 16 + nh * 8);
            u64 sa[4], sb[4], acca[4], accb[4];
            #pragma unroll
            for (int q = 0; q < 4; q++) {
                sa[q] = sta[q]; sb[q] = stb[q];
                acca[q] = 0ull; accb[q] = 0ull;
            }
            #pragma unroll
            for (int i = 0; i < 5; i++) {
                u64 da = 0ull, db = 0ull;
                #pragma unroll
                for (int q = 0; q < 4; q++) {
                    da = ffma2(sa[q], S2h[i][q], da);
                    db = ffma2(sb[q], S2h[i][q], db);
                }
                float la, ha, lb, hb;
                unpack2(da, la, ha); unpack2(db, lb, hb);
                float dsa = la + ha, dsb = lb + hb;
                dsa += __shfl_xor_sync(0xffffffffu, dsa, 1);   // other n-half
                dsb += __shfl_xor_sync(0xffffffffu, dsb, 1);
                float pa = ex2f(dsa + fmaf(xa, U2l[i], Rn[i] + lga));
                float pb = ex2f(dsb + fmaf(xb, U2l[i], Rn[i] + lgb));
                u64 pap = pack2(pa, pa), pbp = pack2(pb, pb);
                #pragma unroll
                for (int q = 0; q < 4; q++) {
                    acca[q] = ffma2(pap, A2h[i][q], acca[q]);
                    accb[q] = ffma2(pbp, A2h[i][q], accb[q]);
                }
            }
            // conflict-free STS: half-buffer base + (b*192+s)*6, two 16B stores
            u64* da_ = part + nhbase + (size_t)(ba * NSLOTS + s) * STR;
            u64* db_ = part + nhbase + (size_t)(bb * NSLOTS + s) * STR;
            *(ulonglong2*)(da_)     = make_ulonglong2(acca[0], acca[1]);
            *(ulonglong2*)(da_ + 2) = make_ulonglong2(acca[2], acca[3]);
            *(ulonglong2*)(db_)     = make_ulonglong2(accb[0], accb[1]);
            *(ulonglong2*)(db_ + 2) = make_ulonglong2(accb[2], accb[3]);
        }
        __syncthreads();

        // reduction: 256 threads = (rb, np, q); interleaved slots i*8+q
        // 4 independent serial chains of 6 (low register pressure), then 2-level tree
        if (tid < 256) {
            const int rb = tid >> 6, np = (tid >> 3) & 7, q = tid & 7;
            const int h = np >> 2, nq = np & 3;
            const u64* base = part + (size_t)h * NHOFF +
                              (size_t)(rb * NSLOTS) * STR + nq;
            u64 c0 = base[(size_t)(0 * 8 + q) * STR];
            u64 c1 = base[(size_t)(1 * 8 + q) * STR];
            u64 c2 = base[(size_t)(2 * 8 + q) * STR];
            u64 c3 = base[(size_t)(3 * 8 + q) * STR];
            #pragma unroll
            for (int i = 1; i < 6; i++) {
                c0 = fadd2(c0, base[(size_t)((4 * i + 0) * 8 + q) * STR]);
                c1 = fadd2(c1, base[(size_t)((4 * i + 1) * 8 + q) * STR]);
                c2 = fadd2(c2, base[(size_t)((4 * i + 2) * 8 + q) * STR]);
                c3 = fadd2(c3, base[(size_t)((4 * i + 3) * 8 + q) * STR]);
            }
            u64 vs = fadd2(fadd2(c0, c1), fadd2(c2, c3));
            #pragma unroll
            for (int o = 1; o < 8; o <<= 1)
                vs = fadd2(vs, __shfl_xor_sync(0xffffffffu, vs, o));
            if (q == 0) {
                float v0, v1;
                unpack2(vs, v0, v1);
                const float f = f_sh[rb];
                float nv0 = v0 * f, nv1 = v1 * f;
                state_sh[rb * 16 + 2 * np]     = nv0;
                state_sh[rb * 16 + 2 * np + 1] = nv1;
                if (np == 7) out[(size_t)(b0 + rb) * T_LEN + t] = nv1;   // n = 15
            }
        }
        __syncthreads();
    }
}

extern "C" void kernel_launch(void* const* d_in, const int* in_sizes, int n_in,
                              void* d_out, int out_size) {
    const float* x  = (const float*)d_in[0];
    const float* S  = (const float*)d_in[1];
    const float* U  = (const float*)d_in[2];
    const float* A  = (const float*)d_in[3];
    const float* W1 = (const float*)d_in[4];
    const float* b1 = (const float*)d_in[5];
    const float* W2 = (const float*)d_in[6];
    const float* b2 = (const float*)d_in[7];
    const int B = in_sizes[0] / T_LEN;   // 512

    static int smem_set = 0;
    if (!smem_set) {
        cudaFuncSetAttribute(kaarma_kernel,
                             cudaFuncAttributeMaxDynamicSharedMemorySize, SMEM_BYTES);
        smem_set = 1;
    }
    gate_kernel<<<(B * T_LEN + 255) / 256, 256>>>(x, W1, b1, W2, b2, B);
    kaarma_kernel<<<B / 4, NTHREADS, SMEM_BYTES>>>(x, S, U, A, (float*)d_out, B);
}

// round 11
// speedup vs baseline: 6.0810x; 1.0220x over previous
#include <cuda_runtime.h>

#define T_LEN 2048
#define C_ 8
#define N_ 16
#define NTHREADS 384
#define WPSTRIDE 13                 // u64 stride for (b,np) row in wp (bank-verified)
#define L2E 1.4426950408889634f

__device__ float g_lgate[(size_t)T_LEN * 512 * C_];   // log2(gate) [t][b][c]

typedef unsigned long long u64;
typedef unsigned int u32;

__device__ __forceinline__ u64 ffma2(u64 a, u64 b, u64 c) {
    u64 d; asm("fma.rn.f32x2 %0, %1, %2, %3;" : "=l"(d) : "l"(a), "l"(b), "l"(c)); return d;
}
__device__ __forceinline__ u64 pack2(float lo, float hi) {
    u64 d; asm("mov.b64 %0, {%1, %2};" : "=l"(d) : "f"(lo), "f"(hi)); return d;
}
__device__ __forceinline__ void unpack2(u64 v, float& lo, float& hi) {
    asm("mov.b64 {%0, %1}, %2;" : "=f"(lo), "=f"(hi) : "l"(v));
}
__device__ __forceinline__ float ex2f(float a) {
    float r; asm("ex2.approx.f32 %0, %1;" : "=f"(r) : "f"(a)); return r;
}
#define ONE2 0x3f8000003f800000ull
__device__ __forceinline__ u64 fadd2(u64 a, u64 b) { return ffma2(a, ONE2, b); }
__device__ __forceinline__ u64 shflx64(u64 v, int m) {
    u32 lo, hi;
    asm("mov.b64 {%0, %1}, %2;" : "=r"(lo), "=r"(hi) : "l"(v));
    lo = __shfl_xor_sync(0xffffffffu, lo, m);
    hi = __shfl_xor_sync(0xffffffffu, hi, m);
    u64 d; asm("mov.b64 %0, {%1, %2};" : "=l"(d) : "r"(lo), "r"(hi));
    return d;
}

// ---------- gate pre-pass: log2(softmax) ----------
__global__ void gate_kernel(const float* __restrict__ x,
                            const float* __restrict__ W1, const float* __restrict__ b1,
                            const float* __restrict__ W2, const float* __restrict__ b2,
                            int B) {
    int idx = blockIdx.x * blockDim.x + threadIdx.x;   // t*B + b
    if (idx >= B * T_LEN) return;
    int t = idx / B, b = idx - t * B;
    float xv = __ldg(&x[(size_t)b * T_LEN + t]);
    float lg[C_];
    #pragma unroll
    for (int c = 0; c < C_; c++) lg[c] = __ldg(&b2[c]);
    #pragma unroll
    for (int j = 0; j < 16; j++) {
        float h = fmaxf(0.f, fmaf(xv, __ldg(&W1[j]), __ldg(&b1[j])));
        #pragma unroll
        for (int c = 0; c < C_; c++) lg[c] = fmaf(h, __ldg(&W2[j * C_ + c]), lg[c]);
    }
    float mx = lg[0];
    #pragma unroll
    for (int c = 1; c < C_; c++) mx = fmaxf(mx, lg[c]);
    float se = 0.f;
    #pragma unroll
    for (int c = 0; c < C_; c++) se += __expf(lg[c] - mx);
    float lse = __log2f(se);
    float* dst = &g_lgate[(size_t)idx * C_];
    #pragma unroll
    for (int c = 0; c < C_; c++) dst[c] = (lg[c] - mx) * L2E - lse;   // log2(gate_c)
}

// ---------- main recurrence: 384 threads, n-half split, in-warp butterfly ----------
__global__ __launch_bounds__(NTHREADS, 1)
void kaarma_kernel(const float* __restrict__ x, const float* __restrict__ S,
                   const float* __restrict__ U, const float* __restrict__ A,
                   float* __restrict__ out, int B) {
    __shared__ u64 wp[4 * 8 * WPSTRIDE];     // 416 u64 = 3.3 KB warp partials
    __shared__ float state_sh[64];           // [4][16]
    __shared__ float gate_sh[64];            // [2][32] double-buffered
    __shared__ float f_sh[4];

    const int tid  = threadIdx.x;
    const int b0   = blockIdx.x * 4;
    const int lane = tid & 31;
    const int wid  = tid >> 5;

    const int nh = tid & 1;                  // n-half
    const int s  = tid >> 1;                 // slot 0..191
    const int c  = s / 24;
    const int j  = s - c * 24;               // j<20 -> 4 rows, j>=20 -> 5 rows
    const int nr = (j < 20) ? 4 : 5;
    const int r0 = (j < 20) ? j * 4 : 80 + (j - 20) * 5;

    const int s0 = (lane >> 1) & 1, s1 = (lane >> 2) & 1;
    const int s2 = (lane >> 3) & 1, s3 = (lane >> 4) & 1;

    // dictionary halves (log2-domain prescale); padded rows zero -> contribute 0
    u64 S2h[5][4], A2h[5][4];
    float U2l[5], Rn[5];
    #pragma unroll
    for (int i = 0; i < 5; i++) {
        if (i < nr) {
            const int g    = c * 100 + r0 + i;
            const int base = g * N_;
            float sv[N_], rr = 0.f;
            #pragma unroll
            for (int n = 0; n < N_; n++) { sv[n] = S[base + n]; rr = fmaf(sv[n], sv[n], rr); }
            float uv = U[g];
            Rn[i]  = -L2E * fmaf(uv, uv, rr);
            U2l[i] = 2.f * L2E * uv;
            #pragma unroll
            for (int q = 0; q < 4; q++) {
                int n0 = nh * 8 + 2 * q;
                S2h[i][q] = pack2(2.f * L2E * sv[n0], 2.f * L2E * sv[n0 + 1]);
                A2h[i][q] = pack2(A[base + n0], A[base + n0 + 1]);
            }
        } else {
            Rn[i] = 0.f; U2l[i] = 0.f;
            #pragma unroll
            for (int q = 0; q < 4; q++) { S2h[i][q] = 0ull; A2h[i][q] = 0ull; }
        }
    }
    if (tid < 64) state_sh[tid] = 0.f;
    if (tid < 32) gate_sh[tid] = __ldg(&g_lgate[(size_t)b0 * C_ + tid]);   // t=0 buffer
    __syncthreads();

    const float* xrow = x + (size_t)b0 * T_LEN;

    for (int t = 0; t < T_LEN; t++) {
        const int cur = t & 1;
        float xv[4];
        #pragma unroll
        for (int b = 0; b < 4; b++) xv[b] = __ldg(xrow + (size_t)b * T_LEN + t);

        // side duties (overlapped with main FMA)
        if (tid >= 256 && tid < 260) {
            const int b = tid - 256;                   // f_b = exp(-(||s||^2+x^2))
            float q = xv[b] * xv[b];
            #pragma unroll
            for (int n = 0; n < N_; n++) {
                float sv = state_sh[b * 16 + n];
                q = fmaf(sv, sv, q);
            }
            f_sh[b] = ex2f(-L2E * q);
        }
        if (tid >= 288 && tid < 320) {                 // prefetch next lgate
            const int ln = tid - 288;
            int tn = (t + 1 < T_LEN) ? t + 1 : t;
            gate_sh[(cur ^ 1) * 32 + ln] =
                __ldg(&g_lgate[((size_t)tn * B + b0) * C_ + ln]);
        }

        // main: two passes over batch pairs
        #pragma unroll
        for (int p = 0; p < 2; p++) {
            const int ba = 2 * p, bb = 2 * p + 1;
            const float xa = xv[ba], xb = xv[bb];
            const float lga = gate_sh[cur * 32 + ba * C_ + c];
            const float lgb = gate_sh[cur * 32 + bb * C_ + c];
            const float x_my  = nh ? xb : xa;
            const float lg_my = nh ? lgb : lga;
            const u64* sta = (const u64*)(state_sh + ba * 16 + nh * 8);
            const u64* stb = (const u64*)(state_sh + bb * 16 + nh * 8);
            u64 sa[4], sb[4], acca[4], accb[4];
            #pragma unroll
            for (int q = 0; q < 4; q++) {
                sa[q] = sta[q]; sb[q] = stb[q];
                acca[q] = 0ull; accb[q] = 0ull;
            }
            #pragma unroll
            for (int i = 0; i < 5; i++) {
                u64 da = 0ull, db = 0ull;
                #pragma unroll
                for (int q = 0; q < 4; q++) {
                    da = ffma2(sa[q], S2h[i][q], da);
                    db = ffma2(sb[q], S2h[i][q], db);
                }
                float la, ha, lb, hb;
                unpack2(da, la, ha); unpack2(db, lb, hb);
                float ha_my = la + ha;            // my half-dot, batch a
                float hb_my = lb + hb;            // my half-dot, batch b
                // single exchange: send the half the PARTNER completes.
                // nh0 completes batch a (needs partner's a-half, sends its b-half);
                // nh1 completes batch b.
                float snd = nh ? ha_my : hb_my;
                float got = __shfl_xor_sync(0xffffffffu, snd, 1);
                float full = (nh ? hb_my : ha_my) + got;
                float my_p = ex2f(full + fmaf(x_my, U2l[i], Rn[i] + lg_my));
                float oth  = __shfl_xor_sync(0xffffffffu, my_p, 1);
                float pa = nh ? oth : my_p;
                float pb = nh ? my_p : oth;
                u64 pap = pack2(pa, pa), pbp = pack2(pb, pb);
                #pragma unroll
                for (int q = 0; q < 4; q++) {
                    acca[q] = ffma2(pap, A2h[i][q], acca[q]);
                    accb[q] = ffma2(pbp, A2h[i][q], accb[q]);
                }
            }
            // in-warp split-butterfly over the warp's 16 slots (lane bits 1..4)
            // L0 (xor 2): keep batch == s0
            u64 v4[4];
            #pragma unroll
            for (int q = 0; q < 4; q++) {
                u64 snd = s0 ? acca[q] : accb[q];
                u64 kp  = s0 ? accb[q] : acca[q];
                v4[q] = fadd2(kp, shflx64(snd, 2));
            }
            // L1 (xor 4): keep q>>1 == s1
            u64 v2[2];
            #pragma unroll
            for (int r = 0; r < 2; r++) {
                u64 snd = s1 ? v4[r] : v4[2 + r];
                u64 kp  = s1 ? v4[2 + r] : v4[r];
                v2[r] = fadd2(kp, shflx64(snd, 4));
            }
            // L2 (xor 8): keep q&1 == s2
            {
                u64 snd = s2 ? v2[0] : v2[1];
                u64 kp  = s2 ? v2[1] : v2[0];
                v2[0] = fadd2(kp, shflx64(snd, 8));
            }
            // L3 (xor 16): plain butterfly
            u64 vw = fadd2(v2[0], shflx64(v2[0], 16));
            // lane (nh,s0,s1,s2) owns sum for batch = 2p+s0, npair = nh*4+s1*2+s2
            if (s3 == 0)
                wp[((2 * p + s0) * 8 + nh * 4 + s1 * 2 + s2) * WPSTRIDE + wid] = vw;
        }
        __syncthreads();

        // final reduce: 128 threads = (b, np, g); sum 12 warp partials
        if (tid < 128) {
            const int rb = tid >> 5, np = (tid >> 2) & 7, g = tid & 3;
            const u64* row = &wp[(rb * 8 + np) * WPSTRIDE];
            u64 v = fadd2(fadd2(row[g], row[g + 4]), row[g + 8]);
            v = fadd2(v, shflx64(v, 1));
            v = fadd2(v, shflx64(v, 2));
            if (g == 0) {
                float v0, v1;
                unpack2(v, v0, v1);
                const float f = f_sh[rb];
                float nv0 = v0 * f, nv1 = v1 * f;
                state_sh[rb * 16 + 2 * np]     = nv0;
                state_sh[rb * 16 + 2 * np + 1] = nv1;
                if (np == 7) out[(size_t)(b0 + rb) * T_LEN + t] = nv1;   // n = 15
            }
        }
        __syncthreads();
    }
}

extern "C" void kernel_launch(void* const* d_in, const int* in_sizes, int n_in,
                              void* d_out, int out_size) {
    const float* x  = (const float*)d_in[0];
    const float* S  = (const float*)d_in[1];
    const float* U  = (const float*)d_in[2];
    const float* A  = (const float*)d_in[3];
    const float* W1 = (const float*)d_in[4];
    const float* b1 = (const float*)d_in[5];
    const float* W2 = (const float*)d_in[6];
    const float* b2 = (const float*)d_in[7];
    const int B = in_sizes[0] / T_LEN;   // 512

    gate_kernel<<<(B * T_LEN + 255) / 256, 256>>>(x, W1, b1, W2, b2, B);
    kaarma_kernel<<<B / 4, NTHREADS>>>(x, S, U, A, (float*)d_out, B);
}